// round 6
// baseline (speedup 1.0000x reference)
#include <cuda_runtime.h>
#include <math.h>

// Problem shape (fixed by dataset): B=32, L=8192, K=64, 20 amino acids.
#define B_DIM 32
#define L_DIM 8192
#define K_DIM 64
#define THREADS 256
#define WARPS (THREADS / 32)
#define TILE_ROWS 128               // grid = 32 x 64 = 2048 blocks
#define ROWS_PER_STEP (WARPS * 4)   // 32 rows per pipeline step
#define STEPS (TILE_ROWS / ROWS_PER_STEP)  // 4

__global__ __launch_bounds__(THREADS, 5)
void hp_pairs_kernel(const int* __restrict__ seq,
                     const float* __restrict__ r,
                     const int* __restrict__ j_idx,
                     const float* __restrict__ h,
                     const float* __restrict__ r_half_raw,
                     const float* __restrict__ tau_hp_raw,
                     const int* __restrict__ max_dist,
                     float* __restrict__ out)
{
    __shared__ float s_hseq[L_DIM];   // h[seq[b, :]] for this batch row (32 KB)

    const int b    = blockIdx.x;
    const int tile = blockIdx.y;
    const int tid  = threadIdx.x;
    const int lane = tid & 31;
    const int warp = tid >> 5;

    // Each lane holds one h-table entry (20 entries <= 32 lanes).
    const float h_lane = h[min(lane, 19)];

    // Mapping: 8 lanes per row, 4 rows per warp, 32 rows per step.
    const int l8   = lane & 7;
    const int rgrp = lane >> 3;
    const int row0 = tile * TILE_ROWS + warp * 4 + rgrp;

    const float* rp = r     + ((size_t)b * L_DIM + row0) * K_DIM + l8 * 4;
    const int*   jp = j_idx + ((size_t)b * L_DIM + row0) * K_DIM + l8 * 4;
    float*       ob = out   + (size_t)b * L_DIM;

    // ---- prefetch step 0 BEFORE staging: DRAM streaming starts immediately ----
    float4 rbuf[2][2];
    int4   jbuf[2][2];
    jbuf[0][0] = __ldcs((const int4*)jp);
    jbuf[0][1] = __ldcs((const int4*)(jp + 32));
    rbuf[0][0] = __ldcs((const float4*)rp);
    rbuf[0][1] = __ldcs((const float4*)(rp + 32));

    // ---- stage h[seq[b,:]] into smem (L2-sourced; overlaps with prefetch) ----
    {
        const int4* src = (const int4*)(seq + b * L_DIM);
        float4*     dst = (float4*)s_hseq;
        #pragma unroll 2
        for (int it = 0; it < L_DIM / 4 / THREADS; ++it) {
            int4 s4 = src[tid + it * THREADS];
            float4 v;
            v.x = __shfl_sync(0xffffffffu, h_lane, s4.x);
            v.y = __shfl_sync(0xffffffffu, h_lane, s4.y);
            v.z = __shfl_sync(0xffffffffu, h_lane, s4.z);
            v.w = __shfl_sync(0xffffffffu, h_lane, s4.w);
            dst[tid + it * THREADS] = v;
        }
    }

    // Scalars. g = exp(-(r-rp)^2/(2 s^2)) = 2^( qa*r^2 + qb*r + qc ), qa<0.
    const float md     = (float)(*max_dist);
    const float r_peak = log1pf(expf(*r_half_raw));
    const float sigma  = log1pf(expf(*tau_hp_raw)) + 0.1f;
    const float qa     = -1.44269504088896340736f / (2.0f * sigma * sigma);
    const float qb     = -2.0f * qa * r_peak;
    const float qc     = qa * r_peak * r_peak;
    const float thresh = md - 1e-4f;

    __syncthreads();

    #pragma unroll
    for (int s = 0; s < STEPS; ++s) {
        const int cur = s & 1;
        // ---- issue next step's loads before consuming current (pipeline) ----
        if (s + 1 < STEPS) {
            const int nxt = cur ^ 1;
            const int*   jn = jp + (size_t)(s + 1) * (ROWS_PER_STEP * K_DIM);
            const float* rn = rp + (size_t)(s + 1) * (ROWS_PER_STEP * K_DIM);
            jbuf[nxt][0] = __ldcs((const int4*)jn);
            jbuf[nxt][1] = __ldcs((const int4*)(jn + 32));
            rbuf[nxt][0] = __ldcs((const float4*)rn);
            rbuf[nxt][1] = __ldcs((const float4*)(rn + 32));
        }

        // ---- consume current step ----
        float acc = 0.0f;
        #pragma unroll
        for (int p = 0; p < 2; ++p) {
            const float4 rv = rbuf[cur][p];
            const int4   jv = jbuf[cur][p];

            // inputs guaranteed in [0, L); mask keeps smem access in bounds
            const float hj0 = s_hseq[jv.x & (L_DIM - 1)];
            const float hj1 = s_hseq[jv.y & (L_DIM - 1)];
            const float hj2 = s_hseq[jv.z & (L_DIM - 1)];
            const float hj3 = s_hseq[jv.w & (L_DIM - 1)];

            float t0 = fmaf(fmaf(qa, rv.x, qb), rv.x, qc);
            float t1 = fmaf(fmaf(qa, rv.y, qb), rv.y, qc);
            float t2 = fmaf(fmaf(qa, rv.z, qb), rv.z, qc);
            float t3 = fmaf(fmaf(qa, rv.w, qb), rv.w, qc);

            // zero invalid lanes via exponent: 2^-350 flushes to 0
            t0 = (rv.x < thresh) ? t0 : -350.0f;
            t1 = (rv.y < thresh) ? t1 : -350.0f;
            t2 = (rv.z < thresh) ? t2 : -350.0f;
            t3 = (rv.w < thresh) ? t3 : -350.0f;

            float g0, g1, g2, g3;
            asm("ex2.approx.ftz.f32 %0, %1;" : "=f"(g0) : "f"(t0));
            asm("ex2.approx.ftz.f32 %0, %1;" : "=f"(g1) : "f"(t1));
            asm("ex2.approx.ftz.f32 %0, %1;" : "=f"(g2) : "f"(t2));
            asm("ex2.approx.ftz.f32 %0, %1;" : "=f"(g3) : "f"(t3));

            acc = fmaf(hj0, g0, acc);
            acc = fmaf(hj1, g1, acc);
            acc = fmaf(hj2, g2, acc);
            acc = fmaf(hj3, g3, acc);
        }

        // reduce over the 8 lanes holding this row (3 chained shfl)
        acc += __shfl_xor_sync(0xffffffffu, acc, 4);
        acc += __shfl_xor_sync(0xffffffffu, acc, 2);
        acc += __shfl_xor_sync(0xffffffffu, acc, 1);

        const int row = row0 + s * ROWS_PER_STEP;
        if (l8 == 0)
            ob[row] = s_hseq[row] * acc;
    }
}

extern "C" void kernel_launch(void* const* d_in, const int* in_sizes, int n_in,
                              void* d_out, int out_size)
{
    // metadata order: seq, r, j_idx, h, r_half_raw, tau_hp_raw, max_dist
    const int*   seq        = (const int*)d_in[0];
    const float* r          = (const float*)d_in[1];
    const int*   j_idx      = (const int*)d_in[2];
    const float* h          = (const float*)d_in[3];
    const float* r_half_raw = (const float*)d_in[4];
    const float* tau_hp_raw = (const float*)d_in[5];
    const int*   max_dist   = (const int*)d_in[6];
    float*       out        = (float*)d_out;

    dim3 grid(B_DIM, L_DIM / TILE_ROWS);   // 32 x 64 = 2048 blocks
    hp_pairs_kernel<<<grid, THREADS>>>(seq, r, j_idx, h,
                                       r_half_raw, tau_hp_raw, max_dist, out);
}

// round 7
// speedup vs baseline: 1.3478x; 1.3478x over previous
#include <cuda_runtime.h>
#include <math.h>

// Problem shape (fixed by dataset): B=32, L=8192, K=64, 20 amino acids.
#define B_DIM 32
#define L_DIM 8192
#define K_DIM 64
#define THREADS 256
#define WARPS (THREADS / 32)
#define UNROLL 2
#define ROWS_PER_U  (WARPS * 4)            // 32 rows per unroll step
#define ROWS_PER_MI (ROWS_PER_U * UNROLL)  // 64 rows per macro-iter
#define TILE_ROWS 128                      // grid = 32 x 64 = 2048 blocks

__global__ __launch_bounds__(THREADS, 5)
void hp_pairs_kernel(const int* __restrict__ seq,
                     const float* __restrict__ r,
                     const int* __restrict__ j_idx,
                     const float* __restrict__ h,
                     const float* __restrict__ r_half_raw,
                     const float* __restrict__ tau_hp_raw,
                     const int* __restrict__ max_dist,
                     float* __restrict__ out)
{
    __shared__ float s_hseq[L_DIM];   // h[seq[b, :]] for this batch row (32 KB)

    const int b    = blockIdx.x;
    const int tile = blockIdx.y;
    const int tid  = threadIdx.x;
    const int lane = tid & 31;
    const int warp = tid >> 5;

    // Each lane holds one h-table entry (20 entries <= 32 lanes).
    const float h_lane = h[min(lane, 19)];

    // Stage h[seq[b,:]] into smem: LDG.128 seq -> 4x shfl lookup -> STS.128.
    {
        const int4* src = (const int4*)(seq + b * L_DIM);
        float4*     dst = (float4*)s_hseq;
        #pragma unroll
        for (int it = 0; it < L_DIM / 4 / THREADS; ++it) {
            int4 s4 = src[tid + it * THREADS];
            float4 v;
            v.x = __shfl_sync(0xffffffffu, h_lane, s4.x);
            v.y = __shfl_sync(0xffffffffu, h_lane, s4.y);
            v.z = __shfl_sync(0xffffffffu, h_lane, s4.z);
            v.w = __shfl_sync(0xffffffffu, h_lane, s4.w);
            dst[tid + it * THREADS] = v;
        }
    }

    // Scalars. g = exp(-(r-rp)^2/(2 s^2)) = 2^( qa*r^2 + qb*r + qc ), qa<0.
    const float md     = (float)(*max_dist);
    const float r_peak = log1pf(expf(*r_half_raw));
    const float sigma  = log1pf(expf(*tau_hp_raw)) + 0.1f;
    const float qa     = -1.44269504088896340736f / (2.0f * sigma * sigma);
    const float qb     = -2.0f * qa * r_peak;
    const float qc     = qa * r_peak * r_peak;
    const float thresh = md - 1e-4f;

    __syncthreads();

    // Mapping: 8 lanes per row, 4 rows per warp.
    const int l8   = lane & 7;
    const int rgrp = lane >> 3;
    const int rowbase = tile * TILE_ROWS + warp * 4 + rgrp;

    const float* rb = r     + ((size_t)b * L_DIM) * K_DIM;
    const int*   jb = j_idx + ((size_t)b * L_DIM) * K_DIM;
    float*       ob = out   + (size_t)b * L_DIM;

    #pragma unroll
    for (int mi = 0; mi < TILE_ROWS / ROWS_PER_MI; ++mi) {
        // ---- batched load phase: 8 independent LDG.128 (4 KB/warp) ----
        float4 ra[UNROLL][2];
        int4   ja[UNROLL][2];
        int    rowA[UNROLL];
        #pragma unroll
        for (int u = 0; u < UNROLL; ++u) {
            const int row = rowbase + mi * ROWS_PER_MI + u * ROWS_PER_U;
            rowA[u] = row;
            const float* rp = rb + (size_t)row * K_DIM + l8 * 4;
            const int*   jp = jb + (size_t)row * K_DIM + l8 * 4;
            ja[u][0] = __ldcs((const int4*)jp);
            ja[u][1] = __ldcs((const int4*)(jp + 32));
            ra[u][0] = __ldcs((const float4*)rp);
            ra[u][1] = __ldcs((const float4*)(rp + 32));
        }

        // ---- compute phase ----
        #pragma unroll
        for (int u = 0; u < UNROLL; ++u) {
            float acc = 0.0f;
            #pragma unroll
            for (int p = 0; p < 2; ++p) {
                const float4 rv = ra[u][p];
                const int4   jv = ja[u][p];

                // j_idx generated in [0, L); mask keeps smem access in bounds
                const float hj0 = s_hseq[jv.x & (L_DIM - 1)];
                const float hj1 = s_hseq[jv.y & (L_DIM - 1)];
                const float hj2 = s_hseq[jv.z & (L_DIM - 1)];
                const float hj3 = s_hseq[jv.w & (L_DIM - 1)];

                float t0 = fmaf(fmaf(qa, rv.x, qb), rv.x, qc);
                float t1 = fmaf(fmaf(qa, rv.y, qb), rv.y, qc);
                float t2 = fmaf(fmaf(qa, rv.z, qb), rv.z, qc);
                float t3 = fmaf(fmaf(qa, rv.w, qb), rv.w, qc);

                // invalid lanes -> exponent -350 -> ex2 flushes to 0
                t0 = (rv.x < thresh) ? t0 : -350.0f;
                t1 = (rv.y < thresh) ? t1 : -350.0f;
                t2 = (rv.z < thresh) ? t2 : -350.0f;
                t3 = (rv.w < thresh) ? t3 : -350.0f;

                float g0, g1, g2, g3;
                asm("ex2.approx.ftz.f32 %0, %1;" : "=f"(g0) : "f"(t0));
                asm("ex2.approx.ftz.f32 %0, %1;" : "=f"(g1) : "f"(t1));
                asm("ex2.approx.ftz.f32 %0, %1;" : "=f"(g2) : "f"(t2));
                asm("ex2.approx.ftz.f32 %0, %1;" : "=f"(g3) : "f"(t3));

                acc = fmaf(hj0, g0, acc);
                acc = fmaf(hj1, g1, acc);
                acc = fmaf(hj2, g2, acc);
                acc = fmaf(hj3, g3, acc);
            }

            // reduce over the 8 lanes holding this row (3 chained shfl)
            acc += __shfl_xor_sync(0xffffffffu, acc, 4);
            acc += __shfl_xor_sync(0xffffffffu, acc, 2);
            acc += __shfl_xor_sync(0xffffffffu, acc, 1);

            if (l8 == 0)
                ob[rowA[u]] = s_hseq[rowA[u]] * acc;
        }
    }
}

extern "C" void kernel_launch(void* const* d_in, const int* in_sizes, int n_in,
                              void* d_out, int out_size)
{
    // metadata order: seq, r, j_idx, h, r_half_raw, tau_hp_raw, max_dist
    const int*   seq        = (const int*)d_in[0];
    const float* r          = (const float*)d_in[1];
    const int*   j_idx      = (const int*)d_in[2];
    const float* h          = (const float*)d_in[3];
    const float* r_half_raw = (const float*)d_in[4];
    const float* tau_hp_raw = (const float*)d_in[5];
    const int*   max_dist   = (const int*)d_in[6];
    float*       out        = (float*)d_out;

    dim3 grid(B_DIM, L_DIM / TILE_ROWS);   // 32 x 64 = 2048 blocks
    hp_pairs_kernel<<<grid, THREADS>>>(seq, r, j_idx, h,
                                       r_half_raw, tau_hp_raw, max_dist, out);
}

// round 10
// speedup vs baseline: 1.4486x; 1.0748x over previous
#include <cuda_runtime.h>
#include <math.h>

// Problem shape (fixed by dataset): B=32, L=8192, K=64, 20 amino acids.
#define B_DIM 32
#define L_DIM 8192
#define K_DIM 64
#define THREADS 256
#define WARPS (THREADS / 32)
#define UNROLL 2
#define ROWS_PER_U  (WARPS * 4)            // 32 rows per unroll step
#define CHUNK_ROWS  (ROWS_PER_U * UNROLL)  // 64 rows per chunk
#define N_CHUNKS    (L_DIM / CHUNK_ROWS)   // 128 chunks per batch row
#define BLOCKS_PER_B 23                    // 32 x 23 = 736 blocks = 1 wave @ occ 5

__global__ __launch_bounds__(THREADS, 5)
void hp_pairs_kernel(const int* __restrict__ seq,
                     const float* __restrict__ r,
                     const int* __restrict__ j_idx,
                     const float* __restrict__ h,
                     const float* __restrict__ r_half_raw,
                     const float* __restrict__ tau_hp_raw,
                     const int* __restrict__ max_dist,
                     float* __restrict__ out)
{
    __shared__ float s_hseq[L_DIM];   // h[seq[b, :]] for this batch row (32 KB)

    const int b    = blockIdx.x;
    const int tblk = blockIdx.y;      // 0..22, chunk stride
    const int tid  = threadIdx.x;
    const int lane = tid & 31;
    const int warp = tid >> 5;

    // Each lane holds one h-table entry (20 entries <= 32 lanes).
    const float h_lane = h[min(lane, 19)];

    // Stage h[seq[b,:]] into smem ONCE per block: LDG.128 -> 4x shfl -> STS.128.
    {
        const int4* src = (const int4*)(seq + b * L_DIM);
        float4*     dst = (float4*)s_hseq;
        #pragma unroll
        for (int it = 0; it < L_DIM / 4 / THREADS; ++it) {
            int4 s4 = src[tid + it * THREADS];
            float4 v;
            v.x = __shfl_sync(0xffffffffu, h_lane, s4.x);
            v.y = __shfl_sync(0xffffffffu, h_lane, s4.y);
            v.z = __shfl_sync(0xffffffffu, h_lane, s4.z);
            v.w = __shfl_sync(0xffffffffu, h_lane, s4.w);
            dst[tid + it * THREADS] = v;
        }
    }

    // Scalars. g = exp(-(r-rp)^2/(2 s^2)) = 2^( qa*r^2 + qb*r + qc ), qa<0.
    const float md     = (float)(*max_dist);
    const float r_peak = log1pf(expf(*r_half_raw));
    const float sigma  = log1pf(expf(*tau_hp_raw)) + 0.1f;
    const float qa     = -1.44269504088896340736f / (2.0f * sigma * sigma);
    const float qb     = -2.0f * qa * r_peak;
    const float qc     = qa * r_peak * r_peak;
    const float thresh = md - 1e-4f;

    __syncthreads();

    // Mapping: 8 lanes per row, 4 rows per warp, 32 rows per u-step.
    const int l8   = lane & 7;
    const int rgrp = lane >> 3;
    const int rowoff = warp * 4 + rgrp;

    const float* rb = r     + ((size_t)b * L_DIM) * K_DIM;
    const int*   jb = j_idx + ((size_t)b * L_DIM) * K_DIM;
    float*       ob = out   + (size_t)b * L_DIM;

    // Persistent chunk loop: block tblk handles chunks tblk, tblk+23, ...
    for (int c = tblk; c < N_CHUNKS; c += BLOCKS_PER_B) {
        // ---- batched load phase: 8 independent LDG.128 (4 KB/warp) ----
        float4 ra[UNROLL][2];
        int4   ja[UNROLL][2];
        int    rowA[UNROLL];
        #pragma unroll
        for (int u = 0; u < UNROLL; ++u) {
            const int row = c * CHUNK_ROWS + u * ROWS_PER_U + rowoff;
            rowA[u] = row;
            const float* rp = rb + (size_t)row * K_DIM + l8 * 4;
            const int*   jp = jb + (size_t)row * K_DIM + l8 * 4;
            ja[u][0] = __ldcs((const int4*)jp);
            ja[u][1] = __ldcs((const int4*)(jp + 32));
            ra[u][0] = __ldcs((const float4*)rp);
            ra[u][1] = __ldcs((const float4*)(rp + 32));
        }

        // ---- compute phase ----
        #pragma unroll
        for (int u = 0; u < UNROLL; ++u) {
            float acc = 0.0f;
            #pragma unroll
            for (int p = 0; p < 2; ++p) {
                const float4 rv = ra[u][p];
                const int4   jv = ja[u][p];

                // j_idx generated in [0, L); mask keeps smem access in bounds
                const float hj0 = s_hseq[jv.x & (L_DIM - 1)];
                const float hj1 = s_hseq[jv.y & (L_DIM - 1)];
                const float hj2 = s_hseq[jv.z & (L_DIM - 1)];
                const float hj3 = s_hseq[jv.w & (L_DIM - 1)];

                float t0 = fmaf(fmaf(qa, rv.x, qb), rv.x, qc);
                float t1 = fmaf(fmaf(qa, rv.y, qb), rv.y, qc);
                float t2 = fmaf(fmaf(qa, rv.z, qb), rv.z, qc);
                float t3 = fmaf(fmaf(qa, rv.w, qb), rv.w, qc);

                // invalid lanes -> exponent -350 -> ex2 flushes to 0
                t0 = (rv.x < thresh) ? t0 : -350.0f;
                t1 = (rv.y < thresh) ? t1 : -350.0f;
                t2 = (rv.z < thresh) ? t2 : -350.0f;
                t3 = (rv.w < thresh) ? t3 : -350.0f;

                float g0, g1, g2, g3;
                asm("ex2.approx.ftz.f32 %0, %1;" : "=f"(g0) : "f"(t0));
                asm("ex2.approx.ftz.f32 %0, %1;" : "=f"(g1) : "f"(t1));
                asm("ex2.approx.ftz.f32 %0, %1;" : "=f"(g2) : "f"(t2));
                asm("ex2.approx.ftz.f32 %0, %1;" : "=f"(g3) : "f"(t3));

                acc = fmaf(hj0, g0, acc);
                acc = fmaf(hj1, g1, acc);
                acc = fmaf(hj2, g2, acc);
                acc = fmaf(hj3, g3, acc);
            }

            // reduce over the 8 lanes holding this row (3 chained shfl)
            acc += __shfl_xor_sync(0xffffffffu, acc, 4);
            acc += __shfl_xor_sync(0xffffffffu, acc, 2);
            acc += __shfl_xor_sync(0xffffffffu, acc, 1);

            if (l8 == 0)
                ob[rowA[u]] = s_hseq[rowA[u]] * acc;
        }
    }
}

extern "C" void kernel_launch(void* const* d_in, const int* in_sizes, int n_in,
                              void* d_out, int out_size)
{
    // metadata order: seq, r, j_idx, h, r_half_raw, tau_hp_raw, max_dist
    const int*   seq        = (const int*)d_in[0];
    const float* r          = (const float*)d_in[1];
    const int*   j_idx      = (const int*)d_in[2];
    const float* h          = (const float*)d_in[3];
    const float* r_half_raw = (const float*)d_in[4];
    const float* tau_hp_raw = (const float*)d_in[5];
    const int*   max_dist   = (const int*)d_in[6];
    float*       out        = (float*)d_out;

    dim3 grid(B_DIM, BLOCKS_PER_B);   // 32 x 23 = 736 blocks = single wave
    hp_pairs_kernel<<<grid, THREADS>>>(seq, r, j_idx, h,
                                       r_half_raw, tau_hp_raw, max_dist, out);
}